// round 1
// baseline (speedup 1.0000x reference)
#include <cuda_runtime.h>
#include <cuda_bf16.h>
#include <cstdint>

// Problem constants (fixed shapes per reference)
#define H_DIM 64
#define W_DIM 176
#define D_DIM 112
#define D4    (D_DIM / 4)   // 28 float4 per feature row

// Vectorized no-return fp32 reduction (sm_90+): 16B per instruction.
__device__ __forceinline__ void red_add_v4(float* addr, float a, float b, float c, float d) {
    asm volatile("red.global.add.v4.f32 [%0], {%1, %2, %3, %4};"
                 :: "l"(addr), "f"(a), "f"(b), "f"(c), "f"(d)
                 : "memory");
}

__global__ __launch_bounds__(256, 8)
void bilinear_scatter_kernel(const float2* __restrict__ pos,
                             const float4* __restrict__ feat,
                             float* __restrict__ out,
                             int n)
{
    const int warp = (blockIdx.x * blockDim.x + threadIdx.x) >> 5;
    const int lane = threadIdx.x & 31;
    if (warp >= n) return;

    // Warp-uniform position load (L1 broadcast) + weight computation
    const float2 p = pos[warp];
    const float x = p.x;
    const float y = p.y;
    const float x0f = floorf(x);
    const float y0f = floorf(y);
    const float wx = x - x0f;
    const float wy = y - y0f;
    const int x0 = (int)x0f;
    const int y0 = (int)y0f;
    const int x1 = x0 + 1;
    const int y1 = y0 + 1;

    // Per-corner weights, with reference semantics: zero weight if OOB, clamp index.
    // (Positions are in [0, W-1) x [0, H-1), so OOB is a rare rounding edge case.)
    float w00 = (1.0f - wy) * (1.0f - wx);
    float w01 = (1.0f - wy) * wx;
    float w10 = wy * (1.0f - wx);
    float w11 = wy * wx;

    const bool v_x0 = (x0 >= 0) && (x0 < W_DIM);
    const bool v_x1 = (x1 >= 0) && (x1 < W_DIM);
    const bool v_y0 = (y0 >= 0) && (y0 < H_DIM);
    const bool v_y1 = (y1 >= 0) && (y1 < H_DIM);
    if (!(v_y0 && v_x0)) w00 = 0.0f;
    if (!(v_y0 && v_x1)) w01 = 0.0f;
    if (!(v_y1 && v_x0)) w10 = 0.0f;
    if (!(v_y1 && v_x1)) w11 = 0.0f;

    const int cx0 = min(max(x0, 0), W_DIM - 1);
    const int cx1 = min(max(x1, 0), W_DIM - 1);
    const int cy0 = min(max(y0, 0), H_DIM - 1);
    const int cy1 = min(max(y1, 0), H_DIM - 1);

    // Coalesced feature read: lane i -> float4 i of this point's row
    float4 f = make_float4(0.f, 0.f, 0.f, 0.f);
    if (lane < D4) f = feat[(size_t)warp * D4 + lane];

    const int lane_off = lane * 4;

    // Four corner scatters (warp-uniform branches; inactive high lanes predicated off)
    if (lane < D4) {
        if (w00 != 0.0f) {
            float* a = out + ((size_t)(cy0 * W_DIM + cx0) * D_DIM + lane_off);
            red_add_v4(a, w00 * f.x, w00 * f.y, w00 * f.z, w00 * f.w);
        }
        if (w01 != 0.0f) {
            float* a = out + ((size_t)(cy0 * W_DIM + cx1) * D_DIM + lane_off);
            red_add_v4(a, w01 * f.x, w01 * f.y, w01 * f.z, w01 * f.w);
        }
        if (w10 != 0.0f) {
            float* a = out + ((size_t)(cy1 * W_DIM + cx0) * D_DIM + lane_off);
            red_add_v4(a, w10 * f.x, w10 * f.y, w10 * f.z, w10 * f.w);
        }
        if (w11 != 0.0f) {
            float* a = out + ((size_t)(cy1 * W_DIM + cx1) * D_DIM + lane_off);
            red_add_v4(a, w11 * f.x, w11 * f.y, w11 * f.z, w11 * f.w);
        }
    }
}

extern "C" void kernel_launch(void* const* d_in, const int* in_sizes, int n_in,
                              void* d_out, int out_size)
{
    const float2* pos  = (const float2*)d_in[0];       // (N, 2) f32
    const float4* feat = (const float4*)d_in[1];       // (N, 112) f32, 448B rows -> float4-aligned
    float* out = (float*)d_out;                        // (64, 176, 112) f32

    const int n = in_sizes[0] / 2;

    // Zero-init output (poisoned by harness). Graph-capturable async memset.
    cudaMemsetAsync(out, 0, (size_t)out_size * sizeof(float));

    // Warp per point: 256 threads = 8 points/block
    const int warps_per_block = 256 / 32;
    const int blocks = (n + warps_per_block - 1) / warps_per_block;
    bilinear_scatter_kernel<<<blocks, 256>>>(pos, feat, out, n);
}

// round 2
// speedup vs baseline: 1.1883x; 1.1883x over previous
#include <cuda_runtime.h>
#include <cuda_bf16.h>
#include <cstdint>

// Fixed problem shapes
#define H_DIM 64
#define W_DIM 176
#define D_DIM 112
#define D4    (D_DIM / 4)          // 28 float4 chunks per feature row
#define CH    (H_DIM - 1)          // 63 cell rows
#define CW    (W_DIM - 1)          // 175 cell cols
#define NCELLS (CH * CW)           // 11025
#define MAXN  500000

// Scratch (no allocations allowed -> __device__ globals)
__device__ int g_counts[NCELLS];
__device__ int g_start[NCELLS];
__device__ int g_cursor[NCELLS];
__device__ int g_cellid[MAXN];
__device__ int g_csr[MAXN];

__device__ __forceinline__ void red_add_v4(float* addr, float a, float b, float c, float d) {
    asm volatile("red.global.add.v4.f32 [%0], {%1, %2, %3, %4};"
                 :: "l"(addr), "f"(a), "f"(b), "f"(c), "f"(d)
                 : "memory");
}

// ---------------------------------------------------------------- pass 0: zero counters
__global__ void zero_counts_kernel() {
    int i = blockIdx.x * blockDim.x + threadIdx.x;
    if (i < NCELLS) g_counts[i] = 0;
}

// ---------------------------------------------------------------- pass 1: cell id + histogram
__global__ void count_kernel(const float2* __restrict__ pos, int n) {
    int i = blockIdx.x * blockDim.x + threadIdx.x;
    if (i >= n) return;
    float2 p = pos[i];
    int cx = min(max((int)floorf(p.x), 0), CW - 1);
    int cy = min(max((int)floorf(p.y), 0), CH - 1);
    int cell = cy * CW + cx;
    g_cellid[i] = cell;
    atomicAdd(&g_counts[cell], 1);   // no return use -> RED
}

// ---------------------------------------------------------------- pass 2: exclusive scan (single CTA)
__global__ void scan_kernel() {
    __shared__ int part[1024];
    const int t = threadIdx.x;
    const int C = (NCELLS + 1023) / 1024;   // 11 cells per thread
    const int base = t * C;

    int s = 0;
    #pragma unroll
    for (int j = 0; j < C; j++) {
        int c = base + j;
        if (c < NCELLS) s += g_counts[c];
    }
    part[t] = s;
    __syncthreads();

    // Hillis-Steele inclusive scan over 1024 partials
    for (int off = 1; off < 1024; off <<= 1) {
        int v = (t >= off) ? part[t - off] : 0;
        __syncthreads();
        part[t] += v;
        __syncthreads();
    }

    int run = part[t] - s;   // exclusive prefix for this thread's chunk
    #pragma unroll
    for (int j = 0; j < C; j++) {
        int c = base + j;
        if (c < NCELLS) {
            g_start[c]  = run;
            g_cursor[c] = run;
            run += g_counts[c];
        }
    }
}

// ---------------------------------------------------------------- pass 3: CSR fill
__global__ void fill_kernel(int n) {
    int i = blockIdx.x * blockDim.x + threadIdx.x;
    if (i >= n) return;
    int cell = g_cellid[i];
    int slot = atomicAdd(&g_cursor[cell], 1);
    g_csr[slot] = i;
}

// ---------------------------------------------------------------- pass 4: per-cell gather + tiny scatter
// One CTA per cell (4 warps). Lane k (<28) owns float4 chunk k of all 4 corner accumulators.
__global__ __launch_bounds__(128, 8)
void cell_kernel(const float2* __restrict__ pos,
                 const float4* __restrict__ feat,
                 float* __restrict__ out)
{
    const int cell = blockIdx.x;
    const int cnt  = g_counts[cell];
    if (cnt == 0) return;                   // uniform across CTA
    const int start = g_start[cell];
    const int cy = cell / CW;
    const int cx = cell - cy * CW;

    const int warp = threadIdx.x >> 5;
    const int lane = threadIdx.x & 31;

    float4 a00 = {0,0,0,0}, a01 = {0,0,0,0}, a10 = {0,0,0,0}, a11 = {0,0,0,0};

    for (int i = warp; i < cnt; i += 4) {
        const int idx = g_csr[start + i];           // warp-uniform load
        const float2 p = __ldg(&pos[idx]);          // warp-uniform, L2-resident
        const float wx = p.x - floorf(p.x);
        const float wy = p.y - floorf(p.y);
        const float w00 = (1.0f - wy) * (1.0f - wx);
        const float w01 = (1.0f - wy) * wx;
        const float w10 = wy * (1.0f - wx);
        const float w11 = wy * wx;

        if (lane < D4) {
            const float4 f = feat[(size_t)idx * D4 + lane];   // coalesced 448B row
            a00.x += w00 * f.x; a00.y += w00 * f.y; a00.z += w00 * f.z; a00.w += w00 * f.w;
            a01.x += w01 * f.x; a01.y += w01 * f.y; a01.z += w01 * f.z; a01.w += w01 * f.w;
            a10.x += w10 * f.x; a10.y += w10 * f.y; a10.z += w10 * f.z; a10.w += w10 * f.w;
            a11.x += w11 * f.x; a11.y += w11 * f.y; a11.z += w11 * f.z; a11.w += w11 * f.w;
        }
    }

    // Cross-warp reduction: [warp][corner][D_DIM] floats
    __shared__ float4 s[4][4][D4];          // 4*4*28*16 = 7168 B
    if (lane < D4) {
        s[warp][0][lane] = a00;
        s[warp][1][lane] = a01;
        s[warp][2][lane] = a10;
        s[warp][3][lane] = a11;
    }
    __syncthreads();

    // 112 threads: thread t -> corner t/28, chunk t%28. One RED.v4 each.
    const int t = threadIdx.x;
    if (t < 4 * D4) {
        const int c = t / D4;
        const int k = t - c * D4;
        float4 v0 = s[0][c][k], v1 = s[1][c][k], v2 = s[2][c][k], v3 = s[3][c][k];
        float vx = v0.x + v1.x + v2.x + v3.x;
        float vy = v0.y + v1.y + v2.y + v3.y;
        float vz = v0.z + v1.z + v2.z + v3.z;
        float vw = v0.w + v1.w + v2.w + v3.w;
        const int dy = c >> 1, dx = c & 1;
        float* addr = out + ((size_t)((cy + dy) * W_DIM + (cx + dx)) * D_DIM + k * 4);
        red_add_v4(addr, vx, vy, vz, vw);
    }
}

// ---------------------------------------------------------------- launch
extern "C" void kernel_launch(void* const* d_in, const int* in_sizes, int n_in,
                              void* d_out, int out_size)
{
    const float2* pos  = (const float2*)d_in[0];
    const float4* feat = (const float4*)d_in[1];
    float* out = (float*)d_out;
    const int n = in_sizes[0] / 2;

    cudaMemsetAsync(out, 0, (size_t)out_size * sizeof(float));

    zero_counts_kernel<<<(NCELLS + 255) / 256, 256>>>();
    count_kernel<<<(n + 255) / 256, 256>>>(pos, n);
    scan_kernel<<<1, 1024>>>();
    fill_kernel<<<(n + 255) / 256, 256>>>(n);
    cell_kernel<<<NCELLS, 128>>>(pos, feat, out);
}